// round 1
// baseline (speedup 1.0000x reference)
#include <cuda_runtime.h>
#include <math.h>

// Problem constants
#define Bn 2048
#define Fn 64
#define Dn 128
#define Hn 8
#define Pn 64

namespace {
constexpr int THREADS = 256;
// padded leading dims (floats) to avoid SMEM bank conflicts; multiples of 4 for float4
constexpr int LDE = 132;   // e tile rows of 128
constexpr int LDW = 68;    // W slice rows of 64
constexpr int LDT = 68;    // 64x64 work tiles

constexpr int OFF_E    = 0;                    // 64*132
constexpr int OFF_WS   = OFF_E  + 64 * LDE;    // 128*68
constexpr int OFF_Q    = OFF_WS + 128 * LDW;   // 64*68 (also reused for AV)
constexpr int OFF_KT   = OFF_Q  + 64 * LDT;
constexpr int OFF_V    = OFF_KT + 64 * LDT;
constexpr int OFF_R    = OFF_V  + 64 * LDT;
constexpr int OFF_S    = OFF_R  + 64 * LDT;
constexpr int OFF_STAT = OFF_S  + 64 * LDT;    // 64 floats (1/colsum)
constexpr int OFF_RED  = OFF_STAT + 64;        // 8 floats (warp partials)
constexpr int OFF_IDX  = OFF_RED + 8;          // 64 ints
constexpr int SMEM_FLOATS = OFF_IDX + 64;
constexpr int SMEM_BYTES  = SMEM_FLOATS * 4;   // ~156 KB
}

// C[64x64] (+ optional transposed store) = A[64xK] * B[Kx64], all in SMEM.
// 16x16 thread grid, 4x4 register tile per thread, float4 SMEM loads.
__device__ __forceinline__ void mm64(const float* __restrict__ A, int lda,
                                     const float* __restrict__ Bm, int ldb,
                                     float* __restrict__ C, int ldc,
                                     int K, bool transStore)
{
    const int tx = threadIdx.x & 15;
    const int ty = threadIdx.x >> 4;
    float acc[4][4];
#pragma unroll
    for (int i = 0; i < 4; i++)
#pragma unroll
        for (int j = 0; j < 4; j++) acc[i][j] = 0.f;

    for (int k = 0; k < K; k += 4) {
        float a[4][4], b[4][4];
#pragma unroll
        for (int i = 0; i < 4; i++) {
            float4 t = *reinterpret_cast<const float4*>(&A[(ty * 4 + i) * lda + k]);
            a[i][0] = t.x; a[i][1] = t.y; a[i][2] = t.z; a[i][3] = t.w;
        }
#pragma unroll
        for (int kk = 0; kk < 4; kk++) {
            float4 t = *reinterpret_cast<const float4*>(&Bm[(k + kk) * ldb + tx * 4]);
            b[kk][0] = t.x; b[kk][1] = t.y; b[kk][2] = t.z; b[kk][3] = t.w;
        }
#pragma unroll
        for (int kk = 0; kk < 4; kk++)
#pragma unroll
            for (int i = 0; i < 4; i++)
#pragma unroll
                for (int j = 0; j < 4; j++)
                    acc[i][j] = fmaf(a[i][kk], b[kk][j], acc[i][j]);
    }
    if (!transStore) {
#pragma unroll
        for (int i = 0; i < 4; i++)
#pragma unroll
            for (int j = 0; j < 4; j++)
                C[(ty * 4 + i) * ldc + tx * 4 + j] = acc[i][j];
    } else {
        // store C^T: used for K so that scores can read K^T with unit stride
#pragma unroll
        for (int i = 0; i < 4; i++)
#pragma unroll
            for (int j = 0; j < 4; j++)
                C[(tx * 4 + j) * ldc + ty * 4 + i] = acc[i][j];
    }
}

__global__ __launch_bounds__(THREADS, 1)
void autoint_kernel(const int*   __restrict__ feat_index,
                    const float* __restrict__ emb,
                    const float* __restrict__ Wq,
                    const float* __restrict__ Wk,
                    const float* __restrict__ Wv,
                    const float* __restrict__ Wr,
                    const float* __restrict__ out_w,
                    const float* __restrict__ out_b,
                    float*       __restrict__ out)
{
    extern __shared__ float sm[];
    float* sE    = sm + OFF_E;
    float* sW    = sm + OFF_WS;
    float* sQ    = sm + OFF_Q;     // q, later av
    float* sKT   = sm + OFF_KT;    // k stored transposed [p][f]
    float* sV    = sm + OFF_V;
    float* sR    = sm + OFF_R;
    float* sS    = sm + OFF_S;     // scores -> att
    float* sStat = sm + OFF_STAT;
    float* sRed  = sm + OFF_RED;
    int*   sIdx  = reinterpret_cast<int*>(sm + OFF_IDX);

    const int b   = blockIdx.x;
    const int tid = threadIdx.x;

    if (tid < Fn) sIdx[tid] = feat_index[b * Fn + tid];
    __syncthreads();

    // Gather embeddings: e[f][0:128] = emb_table[idx[f]]
    for (int i = tid; i < Fn * (Dn / 4); i += THREADS) {
        int row = i >> 5;          // Dn/4 = 32 float4 per row
        int c4  = i & 31;
        float4 v = *reinterpret_cast<const float4*>(
            &emb[(size_t)sIdx[row] * Dn + c4 * 4]);
        *reinterpret_cast<float4*>(&sE[row * LDE + c4 * 4]) = v;
    }
    __syncthreads();

    float acc = 0.f;
    const float* Wptrs[4] = {Wq, Wk, Wv, Wr};

    for (int h = 0; h < Hn; h++) {
        // ---- 4 projections: stage W head-slice [128][64], then 64x64x128 GEMM
        for (int m = 0; m < 4; m++) {
            const float* W = Wptrs[m];
            for (int i = tid; i < Dn * (Pn / 4); i += THREADS) {
                int k  = i >> 4;       // Pn/4 = 16 float4 per row
                int c4 = i & 15;
                float4 v = *reinterpret_cast<const float4*>(
                    &W[k * (Hn * Pn) + h * Pn + c4 * 4]);
                *reinterpret_cast<float4*>(&sW[k * LDW + c4 * 4]) = v;
            }
            __syncthreads();
            float* Cdst = (m == 0) ? sQ : (m == 1) ? sKT : (m == 2) ? sV : sR;
            mm64(sE, LDE, sW, LDW, Cdst, LDT, Dn, /*transStore=*/(m == 1));
            __syncthreads();
        }

        // ---- scores S[q][k] = sum_p q[q,p] * k[k,p]  (via K^T in SMEM)
        mm64(sQ, LDT, sKT, LDT, sS, LDT, Pn, false);
        __syncthreads();

        // ---- softmax over the QUERY axis (axis=2): column-wise on S
        if (tid < Fn) {
            int kk = tid;
            float mmax = -3.402823466e38f;
            for (int q = 0; q < Fn; q++) mmax = fmaxf(mmax, sS[q * LDT + kk]);
            float sum = 0.f;
            for (int q = 0; q < Fn; q++) {
                float e = expf(sS[q * LDT + kk] - mmax);
                sS[q * LDT + kk] = e;
                sum += e;
            }
            sStat[kk] = 1.f / sum;
        }
        __syncthreads();
        for (int i = tid; i < Fn * Fn; i += THREADS) {
            int q = i >> 6, kk = i & 63;
            sS[q * LDT + kk] *= sStat[kk];
        }
        __syncthreads();

        // ---- AV[q][p] = sum_k att[q,k] * v[k,p]   (into sQ, q no longer needed)
        mm64(sS, LDT, sV, LDT, sQ, LDT, Fn, false);
        __syncthreads();

        // ---- partial output: sum relu(av + res) * out_w[f*512 + h*64 + p]
        for (int i = tid; i < Fn * Pn; i += THREADS) {
            int f = i >> 6, p = i & 63;
            float v = sQ[f * LDT + p] + sR[f * LDT + p];
            if (v > 0.f)
                acc += v * out_w[f * (Hn * Pn) + h * Pn + p];
        }
        __syncthreads();   // protect sQ/sR/sW before next head reuses them
    }

    // ---- block reduction + sigmoid
#pragma unroll
    for (int o = 16; o; o >>= 1) acc += __shfl_xor_sync(0xffffffffu, acc, o);
    if ((tid & 31) == 0) sRed[tid >> 5] = acc;
    __syncthreads();
    if (tid == 0) {
        float s = 0.f;
#pragma unroll
        for (int w = 0; w < THREADS / 32; w++) s += sRed[w];
        s += out_b[0];
        out[b] = 1.f / (1.f + expf(-s));
    }
}

extern "C" void kernel_launch(void* const* d_in, const int* in_sizes, int n_in,
                              void* d_out, int out_size)
{
    const int*   feat_index = (const int*)  d_in[0];
    const float* emb        = (const float*)d_in[1];
    const float* Wq         = (const float*)d_in[2];
    const float* Wk         = (const float*)d_in[3];
    const float* Wv         = (const float*)d_in[4];
    const float* Wr         = (const float*)d_in[5];
    const float* out_w      = (const float*)d_in[6];
    const float* out_b      = (const float*)d_in[7];
    float*       out        = (float*)d_out;

    // idempotent, capture-safe (non-stream API)
    cudaFuncSetAttribute(autoint_kernel,
                         cudaFuncAttributeMaxDynamicSharedMemorySize, SMEM_BYTES);

    autoint_kernel<<<Bn, THREADS, SMEM_BYTES>>>(
        feat_index, emb, Wq, Wk, Wv, Wr, out_w, out_b, out);
}

// round 2
// speedup vs baseline: 1.0009x; 1.0009x over previous
#include <cuda_runtime.h>
#include <math.h>

// Problem constants
#define Bn 2048
#define Fn 64
#define Dn 128
#define Hn 8
#define Pn 64

namespace {
constexpr int THREADS = 256;
// padded leading dims (floats) to avoid SMEM bank conflicts; multiples of 4 for float4
constexpr int LDE = 132;   // e tile rows of 128
constexpr int LDW = 68;    // W slice rows of 64
constexpr int LDT = 68;    // 64x64 work tiles

constexpr int OFF_E    = 0;                    // 64*132
constexpr int OFF_WS   = OFF_E  + 64 * LDE;    // 128*68
constexpr int OFF_Q    = OFF_WS + 128 * LDW;   // 64*68 (also reused for AV)
constexpr int OFF_KT   = OFF_Q  + 64 * LDT;
constexpr int OFF_V    = OFF_KT + 64 * LDT;
constexpr int OFF_R    = OFF_V  + 64 * LDT;
constexpr int OFF_S    = OFF_R  + 64 * LDT;
constexpr int OFF_STAT = OFF_S  + 64 * LDT;    // 64 floats (1/colsum)
constexpr int OFF_RED  = OFF_STAT + 64;        // 8 floats (warp partials)
constexpr int OFF_IDX  = OFF_RED + 8;          // 64 ints
constexpr int SMEM_FLOATS = OFF_IDX + 64;
constexpr int SMEM_BYTES  = SMEM_FLOATS * 4;   // ~156 KB
}

// C[64x64] (+ optional transposed store) = A[64xK] * B[Kx64], all in SMEM.
// 16x16 thread grid, 4x4 register tile per thread, float4 SMEM loads.
__device__ __forceinline__ void mm64(const float* __restrict__ A, int lda,
                                     const float* __restrict__ Bm, int ldb,
                                     float* __restrict__ C, int ldc,
                                     int K, bool transStore)
{
    const int tx = threadIdx.x & 15;
    const int ty = threadIdx.x >> 4;
    float acc[4][4];
#pragma unroll
    for (int i = 0; i < 4; i++)
#pragma unroll
        for (int j = 0; j < 4; j++) acc[i][j] = 0.f;

    for (int k = 0; k < K; k += 4) {
        float a[4][4], b[4][4];
#pragma unroll
        for (int i = 0; i < 4; i++) {
            float4 t = *reinterpret_cast<const float4*>(&A[(ty * 4 + i) * lda + k]);
            a[i][0] = t.x; a[i][1] = t.y; a[i][2] = t.z; a[i][3] = t.w;
        }
#pragma unroll
        for (int kk = 0; kk < 4; kk++) {
            float4 t = *reinterpret_cast<const float4*>(&Bm[(k + kk) * ldb + tx * 4]);
            b[kk][0] = t.x; b[kk][1] = t.y; b[kk][2] = t.z; b[kk][3] = t.w;
        }
#pragma unroll
        for (int kk = 0; kk < 4; kk++)
#pragma unroll
            for (int i = 0; i < 4; i++)
#pragma unroll
                for (int j = 0; j < 4; j++)
                    acc[i][j] = fmaf(a[i][kk], b[kk][j], acc[i][j]);
    }
    if (!transStore) {
#pragma unroll
        for (int i = 0; i < 4; i++)
#pragma unroll
            for (int j = 0; j < 4; j++)
                C[(ty * 4 + i) * ldc + tx * 4 + j] = acc[i][j];
    } else {
        // store C^T: used for K so that scores can read K^T with unit stride
#pragma unroll
        for (int i = 0; i < 4; i++)
#pragma unroll
            for (int j = 0; j < 4; j++)
                C[(tx * 4 + j) * ldc + ty * 4 + i] = acc[i][j];
    }
}

__global__ __launch_bounds__(THREADS, 1)
void autoint_kernel(const int*   __restrict__ feat_index,
                    const float* __restrict__ emb,
                    const float* __restrict__ Wq,
                    const float* __restrict__ Wk,
                    const float* __restrict__ Wv,
                    const float* __restrict__ Wr,
                    const float* __restrict__ out_w,
                    const float* __restrict__ out_b,
                    float*       __restrict__ out)
{
    extern __shared__ float sm[];
    float* sE    = sm + OFF_E;
    float* sW    = sm + OFF_WS;
    float* sQ    = sm + OFF_Q;     // q, later av
    float* sKT   = sm + OFF_KT;    // k stored transposed [p][f]
    float* sV    = sm + OFF_V;
    float* sR    = sm + OFF_R;
    float* sS    = sm + OFF_S;     // scores -> att
    float* sStat = sm + OFF_STAT;
    float* sRed  = sm + OFF_RED;
    int*   sIdx  = reinterpret_cast<int*>(sm + OFF_IDX);

    const int b   = blockIdx.x;
    const int tid = threadIdx.x;

    if (tid < Fn) sIdx[tid] = feat_index[b * Fn + tid];
    __syncthreads();

    // Gather embeddings: e[f][0:128] = emb_table[idx[f]]
    for (int i = tid; i < Fn * (Dn / 4); i += THREADS) {
        int row = i >> 5;          // Dn/4 = 32 float4 per row
        int c4  = i & 31;
        float4 v = *reinterpret_cast<const float4*>(
            &emb[(size_t)sIdx[row] * Dn + c4 * 4]);
        *reinterpret_cast<float4*>(&sE[row * LDE + c4 * 4]) = v;
    }
    __syncthreads();

    float acc = 0.f;
    const float* Wptrs[4] = {Wq, Wk, Wv, Wr};

    for (int h = 0; h < Hn; h++) {
        // ---- 4 projections: stage W head-slice [128][64], then 64x64x128 GEMM
        for (int m = 0; m < 4; m++) {
            const float* W = Wptrs[m];
            for (int i = tid; i < Dn * (Pn / 4); i += THREADS) {
                int k  = i >> 4;       // Pn/4 = 16 float4 per row
                int c4 = i & 15;
                float4 v = *reinterpret_cast<const float4*>(
                    &W[k * (Hn * Pn) + h * Pn + c4 * 4]);
                *reinterpret_cast<float4*>(&sW[k * LDW + c4 * 4]) = v;
            }
            __syncthreads();
            float* Cdst = (m == 0) ? sQ : (m == 1) ? sKT : (m == 2) ? sV : sR;
            mm64(sE, LDE, sW, LDW, Cdst, LDT, Dn, /*transStore=*/(m == 1));
            __syncthreads();
        }

        // ---- scores S[q][k] = sum_p q[q,p] * k[k,p]  (via K^T in SMEM)
        mm64(sQ, LDT, sKT, LDT, sS, LDT, Pn, false);
        __syncthreads();

        // ---- softmax over the QUERY axis (axis=2): column-wise on S
        if (tid < Fn) {
            int kk = tid;
            float mmax = -3.402823466e38f;
            for (int q = 0; q < Fn; q++) mmax = fmaxf(mmax, sS[q * LDT + kk]);
            float sum = 0.f;
            for (int q = 0; q < Fn; q++) {
                float e = expf(sS[q * LDT + kk] - mmax);
                sS[q * LDT + kk] = e;
                sum += e;
            }
            sStat[kk] = 1.f / sum;
        }
        __syncthreads();
        for (int i = tid; i < Fn * Fn; i += THREADS) {
            int q = i >> 6, kk = i & 63;
            sS[q * LDT + kk] *= sStat[kk];
        }
        __syncthreads();

        // ---- AV[q][p] = sum_k att[q,k] * v[k,p]   (into sQ, q no longer needed)
        mm64(sS, LDT, sV, LDT, sQ, LDT, Fn, false);
        __syncthreads();

        // ---- partial output: sum relu(av + res) * out_w[f*512 + h*64 + p]
        for (int i = tid; i < Fn * Pn; i += THREADS) {
            int f = i >> 6, p = i & 63;
            float v = sQ[f * LDT + p] + sR[f * LDT + p];
            if (v > 0.f)
                acc += v * out_w[f * (Hn * Pn) + h * Pn + p];
        }
        __syncthreads();   // protect sQ/sR/sW before next head reuses them
    }

    // ---- block reduction + sigmoid
#pragma unroll
    for (int o = 16; o; o >>= 1) acc += __shfl_xor_sync(0xffffffffu, acc, o);
    if ((tid & 31) == 0) sRed[tid >> 5] = acc;
    __syncthreads();
    if (tid == 0) {
        float s = 0.f;
#pragma unroll
        for (int w = 0; w < THREADS / 32; w++) s += sRed[w];
        s += out_b[0];
        out[b] = 1.f / (1.f + expf(-s));
    }
}

extern "C" void kernel_launch(void* const* d_in, const int* in_sizes, int n_in,
                              void* d_out, int out_size)
{
    const int*   feat_index = (const int*)  d_in[0];
    const float* emb        = (const float*)d_in[1];
    const float* Wq         = (const float*)d_in[2];
    const float* Wk         = (const float*)d_in[3];
    const float* Wv         = (const float*)d_in[4];
    const float* Wr         = (const float*)d_in[5];
    const float* out_w      = (const float*)d_in[6];
    const float* out_b      = (const float*)d_in[7];
    float*       out        = (float*)d_out;

    // idempotent, capture-safe (non-stream API)
    cudaFuncSetAttribute(autoint_kernel,
                         cudaFuncAttributeMaxDynamicSharedMemorySize, SMEM_BYTES);

    autoint_kernel<<<Bn, THREADS, SMEM_BYTES>>>(
        feat_index, emb, Wq, Wk, Wv, Wr, out_w, out_b, out);
}

// round 5
// speedup vs baseline: 3.2638x; 3.2610x over previous
#include <cuda_runtime.h>
#include <cuda_bf16.h>
#include <cstdint>
#include <math.h>

#define Bn 2048
#define Fn 64
#define Dn 128
#define Hn 8
#define Pn 64

namespace {
// SMEM byte offsets (all 16B-aligned; MMA tiles use padded strides, no swizzle)
constexpr int OFF_IDX = 0;        // 128 int
constexpr int OFF_INV = 512;      // 128 float
constexpr int OFF_RED = 1024;     // 8 float
constexpr int OFF_E   = 1088;     // bf16 [128][136]  stride 272B
constexpr int OFF_W   = OFF_E + 128 * 272;          // bf16 [128][72] stride 144B
constexpr int OFF_S   = OFF_W;                      // fp32 [128][68] stride 272B (overlaps W)
constexpr int OFF_K   = OFF_W + 128 * 272;          // bf16 [128][72]
constexpr int OFF_V   = OFF_K + 128 * 144;          // bf16 [128][72]
constexpr int OFF_ATT = OFF_V + 128 * 144;          // bf16 [128][72]
constexpr int SMEM_BYTES = OFF_ATT + 128 * 144;     // 126016 B
}

__device__ __forceinline__ uint32_t smem_u32(const void* p) {
    uint32_t a;
    asm("{ .reg .u64 t; cvta.to.shared.u64 t, %1; cvt.u32.u64 %0, t; }" : "=r"(a) : "l"(p));
    return a;
}
__device__ __forceinline__ uint32_t pack_bf16x2(float lo, float hi) {
    uint32_t r;
    asm("cvt.rn.bf16x2.f32 %0, %1, %2;" : "=r"(r) : "f"(hi), "f"(lo));
    return r;
}
__device__ __forceinline__ void ldsm4(uint32_t* r, uint32_t addr) {
    asm volatile("ldmatrix.sync.aligned.m8n8.x4.shared.b16 {%0,%1,%2,%3}, [%4];"
                 : "=r"(r[0]), "=r"(r[1]), "=r"(r[2]), "=r"(r[3]) : "r"(addr));
}
__device__ __forceinline__ void ldsm4t(uint32_t* r, uint32_t addr) {
    asm volatile("ldmatrix.sync.aligned.m8n8.x4.trans.shared.b16 {%0,%1,%2,%3}, [%4];"
                 : "=r"(r[0]), "=r"(r[1]), "=r"(r[2]), "=r"(r[3]) : "r"(addr));
}
__device__ __forceinline__ void mma16816(float* c, const uint32_t* a, uint32_t b0, uint32_t b1) {
    asm volatile(
        "mma.sync.aligned.m16n8k16.row.col.f32.bf16.bf16.f32 "
        "{%0,%1,%2,%3}, {%4,%5,%6,%7}, {%8,%9}, {%0,%1,%2,%3};"
        : "+f"(c[0]), "+f"(c[1]), "+f"(c[2]), "+f"(c[3])
        : "r"(a[0]), "r"(a[1]), "r"(a[2]), "r"(a[3]), "r"(b0), "r"(b1));
}

// C[16x64] = E[16x128] @ W[128x64], A from hoisted E frags, B via ldmatrix.trans on sW
__device__ __forceinline__ void run_proj(float acc[32], const uint32_t ea[8][4],
                                         uint32_t wbase, int lane) {
#pragma unroll
    for (int i = 0; i < 32; i++) acc[i] = 0.f;
#pragma unroll
    for (int nt2 = 0; nt2 < 4; nt2++) {
#pragma unroll
        for (int kt = 0; kt < 8; kt++) {
            uint32_t b[4];
            ldsm4t(b, wbase + (kt * 16 + (lane & 15)) * 144
                          + (nt2 * 16 + (lane >> 4) * 8) * 2);
            mma16816(&acc[nt2 * 8],     ea[kt], b[0], b[1]);
            mma16816(&acc[nt2 * 8 + 4], ea[kt], b[2], b[3]);
        }
    }
}

__global__ __launch_bounds__(256, 1)
void autoint_mma(const int*   __restrict__ feat_index,
                 const float* __restrict__ emb,
                 const float* __restrict__ Wq, const float* __restrict__ Wk,
                 const float* __restrict__ Wv, const float* __restrict__ Wr,
                 const float* __restrict__ out_w, const float* __restrict__ out_b,
                 float* __restrict__ out)
{
    extern __shared__ char sm[];
    const uint32_t smb = smem_u32(sm);
    const int tid  = threadIdx.x;
    const int wid  = tid >> 5;
    const int lane = tid & 31;
    const int m0   = wid * 16;        // warp's M-row base (0..112)
    const int bb   = wid >> 2;        // batch slot (0/1)

    int*   sIdx = (int*)(sm + OFF_IDX);
    float* sInv = (float*)(sm + OFF_INV);
    float* sRed = (float*)(sm + OFF_RED);
    float* sS   = (float*)(sm + OFF_S);

    if (tid < 128) sIdx[tid] = feat_index[(size_t)blockIdx.x * 128 + tid];
    __syncthreads();

    // ---- gather E -> bf16 [128][136]
#pragma unroll
    for (int it = 0; it < 32; it++) {
        int i = tid + it * 256;                 // 128*64 bf16x2 elements
        int row = i >> 6, c2 = i & 63;
        float2 v = *(const float2*)(emb + (size_t)sIdx[row] * Dn + 2 * c2);
        *(uint32_t*)(sm + OFF_E + row * 272 + c2 * 4) = pack_bf16x2(v.x, v.y);
    }
    __syncthreads();

    // ---- hoist E A-fragments (K = 128 -> 8 k-tiles)
    uint32_t ea[8][4];
#pragma unroll
    for (int kt = 0; kt < 8; kt++)
        ldsm4(ea[kt], smb + OFF_E + (m0 + (lane & 15)) * 272
                          + (kt * 16 + (lane >> 4) * 8) * 2);

    const float* Ws[4] = {Wk, Wv, Wq, Wr};
    float oacc = 0.f;

    for (int h = 0; h < Hn; h++) {
        uint32_t qf[4][4];
        float racc[32];

        // ================= projections: k, v, q, r =================
#pragma unroll 1
        for (int m = 0; m < 4; m++) {
            // stage W head-slice [128][64] fp32 -> bf16 [128][72]
            const float* W = Ws[m];
#pragma unroll
            for (int it = 0; it < 16; it++) {
                int i = tid + it * 256;         // 128*32 bf16x2
                int row = i >> 5, c2 = i & 31;
                float2 v = *(const float2*)(W + row * (Hn * Pn) + h * Pn + 2 * c2);
                *(uint32_t*)(sm + OFF_W + row * 144 + c2 * 4) = pack_bf16x2(v.x, v.y);
            }
            __syncthreads();

            float acc[32];
            run_proj(acc, ea, smb + OFF_W, lane);

            if (m <= 1) {
                // k -> sK, v -> sV (bf16, C-fragment scatter; generic pointer!)
                char* p0 = sm + ((m == 0) ? OFF_K : OFF_V)
                              + (m0 + (lane >> 2)) * 144 + (lane & 3) * 4;
#pragma unroll
                for (int j = 0; j < 8; j++) {
                    *(uint32_t*)(p0 + j * 16)           = pack_bf16x2(acc[4*j],   acc[4*j+1]);
                    *(uint32_t*)(p0 + 8 * 144 + j * 16) = pack_bf16x2(acc[4*j+2], acc[4*j+3]);
                }
            } else if (m == 2) {
                // q -> A-fragments for scores (C layout == A layout)
#pragma unroll
                for (int kt = 0; kt < 4; kt++) {
                    qf[kt][0] = pack_bf16x2(acc[8*kt],   acc[8*kt+1]);
                    qf[kt][1] = pack_bf16x2(acc[8*kt+2], acc[8*kt+3]);
                    qf[kt][2] = pack_bf16x2(acc[8*kt+4], acc[8*kt+5]);
                    qf[kt][3] = pack_bf16x2(acc[8*kt+6], acc[8*kt+7]);
                }
            } else {
                // r stays in registers (layout matches AV epilogue)
#pragma unroll
                for (int i = 0; i < 32; i++) racc[i] = acc[i];
            }
            __syncthreads();   // sW consumed by all warps before restage / sS overwrite
        }

        // ================= scores: S[16 x 64] = q @ k^T (K = P = 64) =================
        {
            float sacc[32];
#pragma unroll
            for (int i = 0; i < 32; i++) sacc[i] = 0.f;
#pragma unroll
            for (int nt2 = 0; nt2 < 4; nt2++) {
#pragma unroll
                for (int kt = 0; kt < 4; kt++) {
                    uint32_t b[4];   // non-trans: B from sK[f_k][p] ([N][K], k-contig)
                    ldsm4(b, smb + OFF_K
                             + (bb * 64 + nt2 * 16 + (lane >> 4) * 8 + (lane & 7)) * 144
                             + (kt * 16 + ((lane >> 3) & 1) * 8) * 2);
                    mma16816(&sacc[nt2 * 8],     qf[kt], b[0], b[1]);
                    mma16816(&sacc[nt2 * 8 + 4], qf[kt], b[2], b[3]);
                }
            }
            // store fp32 scores (generic pointer)
            char* p0 = sm + OFF_S + (m0 + (lane >> 2)) * 272 + (lane & 3) * 8;
#pragma unroll
            for (int j = 0; j < 8; j++) {
                *(float2*)(p0 + j * 32)           = make_float2(sacc[4*j],   sacc[4*j+1]);
                *(float2*)(p0 + 8 * 272 + j * 32) = make_float2(sacc[4*j+2], sacc[4*j+3]);
            }
        }
        __syncthreads();

        // ================= softmax over QUERY axis (column-wise, faithful) ========
        if (tid < 128) {
            int col = tid & 63, rb = (tid >> 6) * 64;
            float mx = -3.402823466e38f;
#pragma unroll 4
            for (int q = 0; q < 64; q++) mx = fmaxf(mx, sS[(rb + q) * 68 + col]);
            float sum = 0.f;
#pragma unroll 4
            for (int q = 0; q < 64; q++) {
                float e = __expf(sS[(rb + q) * 68 + col] - mx);
                sS[(rb + q) * 68 + col] = e;
                sum += e;
            }
            sInv[tid] = 1.f / sum;
        }
        __syncthreads();

        // ---- att -> bf16 [128][72]
#pragma unroll
        for (int it = 0; it < 16; it++) {
            int i = tid + it * 256;             // 128*32 pairs
            int row = i >> 5, c2 = i & 31;
            const float* inv = sInv + (row >> 6) * 64;
            float a0 = sS[row * 68 + 2 * c2]     * inv[2 * c2];
            float a1 = sS[row * 68 + 2 * c2 + 1] * inv[2 * c2 + 1];
            *(uint32_t*)(sm + OFF_ATT + row * 144 + c2 * 4) = pack_bf16x2(a0, a1);
        }
        __syncthreads();

        // ================= AV[16 x 64] = att @ v (K = 64) =================
        float avacc[32];
        {
            uint32_t af[4][4];
#pragma unroll
            for (int kt = 0; kt < 4; kt++)
                ldsm4(af[kt], smb + OFF_ATT + (m0 + (lane & 15)) * 144
                                  + (kt * 16 + (lane >> 4) * 8) * 2);
#pragma unroll
            for (int i = 0; i < 32; i++) avacc[i] = 0.f;
#pragma unroll
            for (int nt2 = 0; nt2 < 4; nt2++) {
#pragma unroll
                for (int kt = 0; kt < 4; kt++) {
                    uint32_t b[4];   // trans: B from sV[f_k][p] ([K][N], n-contig)
                    ldsm4t(b, smb + OFF_V
                              + (bb * 64 + kt * 16 + (lane & 15)) * 144
                              + (nt2 * 16 + (lane >> 4) * 8) * 2);
                    mma16816(&avacc[nt2 * 8],     af[kt], b[0], b[1]);
                    mma16816(&avacc[nt2 * 8 + 4], af[kt], b[2], b[3]);
                }
            }
        }

        // ================= epilogue: oacc += relu(av + r) * out_w =================
        {
            int frow = (m0 & 63) + (lane >> 2);            // local feature row
            const float* ow = out_w + (size_t)h * Pn + (lane & 3) * 2;
#pragma unroll
            for (int j = 0; j < 8; j++) {
                float2 w0 = *(const float2*)(ow + (size_t)frow * (Hn * Pn) + j * 8);
                float2 w1 = *(const float2*)(ow + (size_t)(frow + 8) * (Hn * Pn) + j * 8);
                float v0 = avacc[4*j]   + racc[4*j];
                float v1 = avacc[4*j+1] + racc[4*j+1];
                float v2 = avacc[4*j+2] + racc[4*j+2];
                float v3 = avacc[4*j+3] + racc[4*j+3];
                if (v0 > 0.f) oacc += v0 * w0.x;
                if (v1 > 0.f) oacc += v1 * w0.y;
                if (v2 > 0.f) oacc += v2 * w1.x;
                if (v3 > 0.f) oacc += v3 * w1.y;
            }
        }
        __syncthreads();   // protect sK/sV/sAtt/sS before next head
    }

    // ---- reduce: warps 0-3 -> batch0, 4-7 -> batch1
#pragma unroll
    for (int o = 16; o; o >>= 1) oacc += __shfl_xor_sync(0xffffffffu, oacc, o);
    if (lane == 0) sRed[wid] = oacc;
    __syncthreads();
    if (tid == 0) {
        float s = sRed[0] + sRed[1] + sRed[2] + sRed[3] + out_b[0];
        out[blockIdx.x * 2] = 1.f / (1.f + expf(-s));
    }
    if (tid == 1) {
        float s = sRed[4] + sRed[5] + sRed[6] + sRed[7] + out_b[0];
        out[blockIdx.x * 2 + 1] = 1.f / (1.f + expf(-s));
    }
}

extern "C" void kernel_launch(void* const* d_in, const int* in_sizes, int n_in,
                              void* d_out, int out_size)
{
    cudaFuncSetAttribute(autoint_mma, cudaFuncAttributeMaxDynamicSharedMemorySize, SMEM_BYTES);
    autoint_mma<<<Bn / 2, 256, SMEM_BYTES>>>(
        (const int*)d_in[0], (const float*)d_in[1],
        (const float*)d_in[2], (const float*)d_in[3],
        (const float*)d_in[4], (const float*)d_in[5],
        (const float*)d_in[6], (const float*)d_in[7], (float*)d_out);
}

// round 6
// speedup vs baseline: 8.3028x; 2.5439x over previous
#include <cuda_runtime.h>
#include <cuda_bf16.h>
#include <cstdint>
#include <math.h>

#define Bn 2048
#define Fn 64
#define Dn 128
#define Hn 8
#define Pn 64

namespace {
// SMEM byte offsets. S (fp32 scores) overlaps W+K: it is only live between
// the post-scores sync and the att-write sync, when sW/sK are dead.
constexpr int OFF_IDX = 0;        // 128 int
constexpr int OFF_INV = 512;      // 128 float
constexpr int OFF_RED = 1024;     // 8 float
constexpr int OFF_E   = 1088;                       // bf16 [128][136] stride 272B
constexpr int OFF_W   = OFF_E + 128 * 272;          // bf16 [128][72]  stride 144B
constexpr int OFF_K   = OFF_W + 128 * 144;          // bf16 [128][72]
constexpr int OFF_S   = OFF_W;                      // fp32 [128][68]  stride 272B (over W+K)
constexpr int OFF_V   = OFF_K + 128 * 144;          // bf16 [128][72]
constexpr int OFF_ATT = OFF_V + 128 * 144;          // bf16 [128][72]
constexpr int SMEM_BYTES = OFF_ATT + 128 * 144;     // 109632 B -> 2 CTAs/SM
}

__device__ __forceinline__ uint32_t smem_u32(const void* p) {
    uint32_t a;
    asm("{ .reg .u64 t; cvta.to.shared.u64 t, %1; cvt.u32.u64 %0, t; }" : "=r"(a) : "l"(p));
    return a;
}
__device__ __forceinline__ uint32_t pack_bf16x2(float lo, float hi) {
    uint32_t r;
    asm("cvt.rn.bf16x2.f32 %0, %1, %2;" : "=r"(r) : "f"(hi), "f"(lo));
    return r;
}
__device__ __forceinline__ void ldsm4(uint32_t* r, uint32_t addr) {
    asm volatile("ldmatrix.sync.aligned.m8n8.x4.shared.b16 {%0,%1,%2,%3}, [%4];"
                 : "=r"(r[0]), "=r"(r[1]), "=r"(r[2]), "=r"(r[3]) : "r"(addr));
}
__device__ __forceinline__ void ldsm4t(uint32_t* r, uint32_t addr) {
    asm volatile("ldmatrix.sync.aligned.m8n8.x4.trans.shared.b16 {%0,%1,%2,%3}, [%4];"
                 : "=r"(r[0]), "=r"(r[1]), "=r"(r[2]), "=r"(r[3]) : "r"(addr));
}
__device__ __forceinline__ void mma16816(float* c, const uint32_t* a, uint32_t b0, uint32_t b1) {
    asm volatile(
        "mma.sync.aligned.m16n8k16.row.col.f32.bf16.bf16.f32 "
        "{%0,%1,%2,%3}, {%4,%5,%6,%7}, {%8,%9}, {%0,%1,%2,%3};"
        : "+f"(c[0]), "+f"(c[1]), "+f"(c[2]), "+f"(c[3])
        : "r"(a[0]), "r"(a[1]), "r"(a[2]), "r"(a[3]), "r"(b0), "r"(b1));
}

// C[16x64] = E[16x128] @ W[128x64]; A frags reloaded from sE per k-tile
// (kt-outer keeps only 4 a-regs live), B via ldmatrix.trans on sW.
__device__ __forceinline__ void run_proj(float acc[32], uint32_t ebase,
                                         uint32_t wbase, int lane) {
#pragma unroll
    for (int i = 0; i < 32; i++) acc[i] = 0.f;
#pragma unroll
    for (int kt = 0; kt < 8; kt++) {
        uint32_t a[4];
        ldsm4(a, ebase + (lane & 15) * 272 + (kt * 16 + (lane >> 4) * 8) * 2);
#pragma unroll
        for (int nt2 = 0; nt2 < 4; nt2++) {
            uint32_t b[4];
            ldsm4t(b, wbase + (kt * 16 + (lane & 15)) * 144
                          + (nt2 * 16 + (lane >> 4) * 8) * 2);
            mma16816(&acc[nt2 * 8],     a, b[0], b[1]);
            mma16816(&acc[nt2 * 8 + 4], a, b[2], b[3]);
        }
    }
}

__device__ __forceinline__ void stage_w(char* sm, const float* W, int h, int tid) {
#pragma unroll
    for (int it = 0; it < 16; it++) {
        int i = tid + it * 256;             // 128*32 bf16x2
        int row = i >> 5, c2 = i & 31;
        float2 v = *(const float2*)(W + row * (Hn * Pn) + h * Pn + 2 * c2);
        *(uint32_t*)(sm + OFF_W + row * 144 + c2 * 4) = pack_bf16x2(v.x, v.y);
    }
}

__global__ __launch_bounds__(256, 2)
void autoint_mma(const int*   __restrict__ feat_index,
                 const float* __restrict__ emb,
                 const float* __restrict__ Wq, const float* __restrict__ Wk,
                 const float* __restrict__ Wv, const float* __restrict__ Wr,
                 const float* __restrict__ out_w, const float* __restrict__ out_b,
                 float* __restrict__ out)
{
    extern __shared__ char sm[];
    const uint32_t smb = smem_u32(sm);
    const int tid  = threadIdx.x;
    const int wid  = tid >> 5;
    const int lane = tid & 31;
    const int m0   = wid * 16;        // warp's M-row base (0..112)
    const int bb   = wid >> 2;        // batch slot (0/1)

    int*   sIdx = (int*)(sm + OFF_IDX);
    float* sInv = (float*)(sm + OFF_INV);
    float* sRed = (float*)(sm + OFF_RED);
    float* sS   = (float*)(sm + OFF_S);

    if (tid < 128) sIdx[tid] = feat_index[(size_t)blockIdx.x * 128 + tid];
    __syncthreads();

    // ---- gather E -> bf16 [128][136]
#pragma unroll
    for (int it = 0; it < 32; it++) {
        int i = tid + it * 256;                 // 128*64 bf16x2 elements
        int row = i >> 6, c2 = i & 63;
        float2 v = *(const float2*)(emb + (size_t)sIdx[row] * Dn + 2 * c2);
        *(uint32_t*)(sm + OFF_E + row * 272 + c2 * 4) = pack_bf16x2(v.x, v.y);
    }
    __syncthreads();

    const uint32_t ebase = smb + OFF_E + m0 * 272;
    float oacc = 0.f;

    for (int h = 0; h < Hn; h++) {
        uint32_t qf[4][4];
        float avacc[32];

        // ================= k and v projections =================
#pragma unroll 1
        for (int m = 0; m < 2; m++) {
            stage_w(sm, (m == 0) ? Wk : Wv, h, tid);
            __syncthreads();
            float acc[32];
            run_proj(acc, ebase, smb + OFF_W, lane);
            char* p0 = sm + ((m == 0) ? OFF_K : OFF_V)
                          + (m0 + (lane >> 2)) * 144 + (lane & 3) * 4;
#pragma unroll
            for (int j = 0; j < 8; j++) {
                *(uint32_t*)(p0 + j * 16)           = pack_bf16x2(acc[4*j],   acc[4*j+1]);
                *(uint32_t*)(p0 + 8 * 144 + j * 16) = pack_bf16x2(acc[4*j+2], acc[4*j+3]);
            }
            __syncthreads();   // sW consumed; sK/sV visible
        }

        // ================= q projection -> A-fragments =================
        stage_w(sm, Wq, h, tid);
        __syncthreads();
        {
            float acc[32];
            run_proj(acc, ebase, smb + OFF_W, lane);
#pragma unroll
            for (int kt = 0; kt < 4; kt++) {
                qf[kt][0] = pack_bf16x2(acc[8*kt],   acc[8*kt+1]);
                qf[kt][1] = pack_bf16x2(acc[8*kt+2], acc[8*kt+3]);
                qf[kt][2] = pack_bf16x2(acc[8*kt+4], acc[8*kt+5]);
                qf[kt][3] = pack_bf16x2(acc[8*kt+6], acc[8*kt+7]);
            }
        }

        // ================= scores: S[16x64] = q @ k^T (K = 64) =================
        {
            float sacc[32];
#pragma unroll
            for (int i = 0; i < 32; i++) sacc[i] = 0.f;
#pragma unroll
            for (int kt = 0; kt < 4; kt++) {
#pragma unroll
                for (int nt2 = 0; nt2 < 4; nt2++) {
                    uint32_t b[4];   // non-trans: B from sK[f_k][p]
                    ldsm4(b, smb + OFF_K
                             + (bb * 64 + nt2 * 16 + (lane >> 4) * 8 + (lane & 7)) * 144
                             + (kt * 16 + ((lane >> 3) & 1) * 8) * 2);
                    mma16816(&sacc[nt2 * 8],     qf[kt], b[0], b[1]);
                    mma16816(&sacc[nt2 * 8 + 4], qf[kt], b[2], b[3]);
                }
            }
            __syncthreads();   // all warps done with sW (q) and sK -> S may overwrite
            char* p0 = sm + OFF_S + (m0 + (lane >> 2)) * 272 + (lane & 3) * 8;
#pragma unroll
            for (int j = 0; j < 8; j++) {
                *(float2*)(p0 + j * 32)           = make_float2(sacc[4*j],   sacc[4*j+1]);
                *(float2*)(p0 + 8 * 272 + j * 32) = make_float2(sacc[4*j+2], sacc[4*j+3]);
            }
        }
        __syncthreads();

        // ================= softmax over QUERY axis (column-wise, faithful) ====
        if (tid < 128) {
            int col = tid & 63, rb = (tid >> 6) * 64;
            float mx = -3.402823466e38f;
#pragma unroll 4
            for (int q = 0; q < 64; q++) mx = fmaxf(mx, sS[(rb + q) * 68 + col]);
            float sum = 0.f;
#pragma unroll 4
            for (int q = 0; q < 64; q++) {
                float e = __expf(sS[(rb + q) * 68 + col] - mx);
                sS[(rb + q) * 68 + col] = e;
                sum += e;
            }
            sInv[tid] = 1.f / sum;
        }
        __syncthreads();

        // ---- att -> bf16 [128][72]
#pragma unroll
        for (int it = 0; it < 16; it++) {
            int i = tid + it * 256;             // 128*32 pairs
            int row = i >> 5, c2 = i & 31;
            const float* inv = sInv + (row >> 6) * 64;
            float a0 = sS[row * 68 + 2 * c2]     * inv[2 * c2];
            float a1 = sS[row * 68 + 2 * c2 + 1] * inv[2 * c2 + 1];
            *(uint32_t*)(sm + OFF_ATT + row * 144 + c2 * 4) = pack_bf16x2(a0, a1);
        }
        __syncthreads();   // S dead; sATT visible

        // ================= AV[16x64] = att @ v (K = 64) =================
#pragma unroll
        for (int i = 0; i < 32; i++) avacc[i] = 0.f;
#pragma unroll
        for (int kt = 0; kt < 4; kt++) {
            uint32_t af[4];
            ldsm4(af, smb + OFF_ATT + (m0 + (lane & 15)) * 144
                          + (kt * 16 + (lane >> 4) * 8) * 2);
#pragma unroll
            for (int nt2 = 0; nt2 < 4; nt2++) {
                uint32_t b[4];   // trans: B from sV[f_k][p]
                ldsm4t(b, smb + OFF_V
                          + (bb * 64 + kt * 16 + (lane & 15)) * 144
                          + (nt2 * 16 + (lane >> 4) * 8) * 2);
                mma16816(&avacc[nt2 * 8],     af, b[0], b[1]);
                mma16816(&avacc[nt2 * 8 + 4], af, b[2], b[3]);
            }
        }

        // ================= r projection (last: reuses acc regs; W over dead S)
        stage_w(sm, Wr, h, tid);
        __syncthreads();
        {
            float acc[32];
            run_proj(acc, ebase, smb + OFF_W, lane);

            // ---- epilogue: oacc += relu(av + r) * out_w
            int frow = (m0 & 63) + (lane >> 2);            // local feature row
            const float* ow = out_w + (size_t)h * Pn + (lane & 3) * 2;
#pragma unroll
            for (int j = 0; j < 8; j++) {
                float2 w0 = *(const float2*)(ow + (size_t)frow * (Hn * Pn) + j * 8);
                float2 w1 = *(const float2*)(ow + (size_t)(frow + 8) * (Hn * Pn) + j * 8);
                float v0 = avacc[4*j]   + acc[4*j];
                float v1 = avacc[4*j+1] + acc[4*j+1];
                float v2 = avacc[4*j+2] + acc[4*j+2];
                float v3 = avacc[4*j+3] + acc[4*j+3];
                if (v0 > 0.f) oacc += v0 * w0.x;
                if (v1 > 0.f) oacc += v1 * w0.y;
                if (v2 > 0.f) oacc += v2 * w1.x;
                if (v3 > 0.f) oacc += v3 * w1.y;
            }
        }
        __syncthreads();   // protect sW/sK/sV/sATT before next head
    }

    // ---- reduce: warps 0-3 -> batch0, 4-7 -> batch1
#pragma unroll
    for (int o = 16; o; o >>= 1) oacc += __shfl_xor_sync(0xffffffffu, oacc, o);
    if (lane == 0) sRed[wid] = oacc;
    __syncthreads();
    if (tid == 0) {
        float s = sRed[0] + sRed[1] + sRed[2] + sRed[3] + out_b[0];
        out[blockIdx.x * 2] = 1.f / (1.f + expf(-s));
    }
    if (tid == 1) {
        float s = sRed[4] + sRed[5] + sRed[6] + sRed[7] + out_b[0];
        out[blockIdx.x * 2 + 1] = 1.f / (1.f + expf(-s));
    }
}

extern "C" void kernel_launch(void* const* d_in, const int* in_sizes, int n_in,
                              void* d_out, int out_size)
{
    cudaFuncSetAttribute(autoint_mma, cudaFuncAttributeMaxDynamicSharedMemorySize, SMEM_BYTES);
    autoint_mma<<<Bn / 2, 256, SMEM_BYTES>>>(
        (const int*)d_in[0], (const float*)d_in[1],
        (const float*)d_in[2], (const float*)d_in[3],
        (const float*)d_in[4], (const float*)d_in[5],
        (const float*)d_in[6], (const float*)d_in[7], (float*)d_out);
}

// round 7
// speedup vs baseline: 8.6214x; 1.0384x over previous
#include <cuda_runtime.h>
#include <cuda_bf16.h>
#include <cstdint>
#include <math.h>

#define Bn 2048
#define Fn 64
#define Dn 128
#define Hn 8
#define Pn 64

namespace {
// SMEM byte offsets (16B-aligned rows; padded strides, no swizzle)
constexpr int OFF_IDX = 0;                    // 128 int
constexpr int OFF_RED = 512;                  // 8 float
constexpr int OFF_XM  = 544;                  // fp32 [4][144] max-exchange
constexpr int OFF_XS  = OFF_XM + 2304;        // fp32 [4][144] sum-exchange
constexpr int OFF_E   = OFF_XS + 2304;        // bf16 [128][136] stride 272B
constexpr int OFF_W   = OFF_E + 128 * 272;    // bf16 [128][72]  stride 144B
constexpr int OFF_K   = OFF_W + 128 * 144;    // bf16 [128][72]
constexpr int OFF_V   = OFF_K + 128 * 144;    // bf16 [128][72]
constexpr int SMEM_BYTES = OFF_V + 128 * 144; // 95264 B -> 2 CTAs/SM
}

__device__ __forceinline__ uint32_t smem_u32(const void* p) {
    uint32_t a;
    asm("{ .reg .u64 t; cvta.to.shared.u64 t, %1; cvt.u32.u64 %0, t; }" : "=r"(a) : "l"(p));
    return a;
}
__device__ __forceinline__ uint32_t pack_bf16x2(float lo, float hi) {
    uint32_t r;
    asm("cvt.rn.bf16x2.f32 %0, %1, %2;" : "=r"(r) : "f"(hi), "f"(lo));
    return r;
}
__device__ __forceinline__ void ldsm4(uint32_t* r, uint32_t addr) {
    asm volatile("ldmatrix.sync.aligned.m8n8.x4.shared.b16 {%0,%1,%2,%3}, [%4];"
                 : "=r"(r[0]), "=r"(r[1]), "=r"(r[2]), "=r"(r[3]) : "r"(addr));
}
__device__ __forceinline__ void ldsm4t(uint32_t* r, uint32_t addr) {
    asm volatile("ldmatrix.sync.aligned.m8n8.x4.trans.shared.b16 {%0,%1,%2,%3}, [%4];"
                 : "=r"(r[0]), "=r"(r[1]), "=r"(r[2]), "=r"(r[3]) : "r"(addr));
}
__device__ __forceinline__ void mma16816(float* c, const uint32_t* a, uint32_t b0, uint32_t b1) {
    asm volatile(
        "mma.sync.aligned.m16n8k16.row.col.f32.bf16.bf16.f32 "
        "{%0,%1,%2,%3}, {%4,%5,%6,%7}, {%8,%9}, {%0,%1,%2,%3};"
        : "+f"(c[0]), "+f"(c[1]), "+f"(c[2]), "+f"(c[3])
        : "r"(a[0]), "r"(a[1]), "r"(a[2]), "r"(a[3]), "r"(b0), "r"(b1));
}

// C[16x64] = E[16x128] @ W[128x64]; A from hoisted E frags, B via ldmatrix.trans on sW
__device__ __forceinline__ void run_proj(float acc[32], const uint32_t ea[8][4],
                                         uint32_t wbase, int lane) {
#pragma unroll
    for (int i = 0; i < 32; i++) acc[i] = 0.f;
#pragma unroll
    for (int kt = 0; kt < 8; kt++) {
#pragma unroll
        for (int nt2 = 0; nt2 < 4; nt2++) {
            uint32_t b[4];
            ldsm4t(b, wbase + (kt * 16 + (lane & 15)) * 144
                          + (nt2 * 16 + (lane >> 4) * 8) * 2);
            mma16816(&acc[nt2 * 8],     ea[kt], b[0], b[1]);
            mma16816(&acc[nt2 * 8 + 4], ea[kt], b[2], b[3]);
        }
    }
}

__device__ __forceinline__ void stage_w(char* sm, const float* W, int h, int tid) {
#pragma unroll
    for (int it = 0; it < 16; it++) {
        int i = tid + it * 256;             // 128*32 bf16x2
        int row = i >> 5, c2 = i & 31;
        float2 v = *(const float2*)(W + row * (Hn * Pn) + h * Pn + 2 * c2);
        *(uint32_t*)(sm + OFF_W + row * 144 + c2 * 4) = pack_bf16x2(v.x, v.y);
    }
}

__global__ __launch_bounds__(256, 2)
void autoint_mma(const int*   __restrict__ feat_index,
                 const float* __restrict__ emb,
                 const float* __restrict__ Wq, const float* __restrict__ Wk,
                 const float* __restrict__ Wv, const float* __restrict__ Wr,
                 const float* __restrict__ out_w, const float* __restrict__ out_b,
                 float* __restrict__ out)
{
    extern __shared__ char sm[];
    const uint32_t smb = smem_u32(sm);
    const int tid  = threadIdx.x;
    const int wid  = tid >> 5;
    const int lane = tid & 31;
    const int m0   = wid * 16;        // warp's M-row base (0..112)
    const int bb   = wid >> 2;        // batch slot (0/1)
    const int w4   = wid & 3;         // warp index within batch

    int*   sIdx = (int*)(sm + OFF_IDX);
    float* sRed = (float*)(sm + OFF_RED);

    if (tid < 128) sIdx[tid] = feat_index[(size_t)blockIdx.x * 128 + tid];
    __syncthreads();

    // ---- gather E -> bf16 [128][136]
#pragma unroll
    for (int it = 0; it < 32; it++) {
        int i = tid + it * 256;                 // 128*64 bf16x2 elements
        int row = i >> 6, c2 = i & 63;
        float2 v = *(const float2*)(emb + (size_t)sIdx[row] * Dn + 2 * c2);
        *(uint32_t*)(sm + OFF_E + row * 272 + c2 * 4) = pack_bf16x2(v.x, v.y);
    }
    __syncthreads();

    // ---- hoist E A-fragments (persist across all heads)
    uint32_t ea[8][4];
#pragma unroll
    for (int kt = 0; kt < 8; kt++)
        ldsm4(ea[kt], smb + OFF_E + (m0 + (lane & 15)) * 272
                          + (kt * 16 + (lane >> 4) * 8) * 2);

    float oacc = 0.f;

    for (int h = 0; h < Hn; h++) {
        uint32_t qf[4][4];

        // ================= k and v projections =================
#pragma unroll 1
        for (int m = 0; m < 2; m++) {
            stage_w(sm, (m == 0) ? Wk : Wv, h, tid);
            __syncthreads();
            float acc[32];
            run_proj(acc, ea, smb + OFF_W, lane);
            char* p0 = sm + ((m == 0) ? OFF_K : OFF_V)
                          + (m0 + (lane >> 2)) * 144 + (lane & 3) * 4;
#pragma unroll
            for (int j = 0; j < 8; j++) {
                *(uint32_t*)(p0 + j * 16)           = pack_bf16x2(acc[4*j],   acc[4*j+1]);
                *(uint32_t*)(p0 + 8 * 144 + j * 16) = pack_bf16x2(acc[4*j+2], acc[4*j+3]);
            }
            __syncthreads();   // sW consumed; sK/sV visible
        }

        // ================= q projection -> A-fragments =================
        stage_w(sm, Wq, h, tid);
        __syncthreads();
        {
            float acc[32];
            run_proj(acc, ea, smb + OFF_W, lane);
#pragma unroll
            for (int kt = 0; kt < 4; kt++) {
                qf[kt][0] = pack_bf16x2(acc[8*kt],   acc[8*kt+1]);
                qf[kt][1] = pack_bf16x2(acc[8*kt+2], acc[8*kt+3]);
                qf[kt][2] = pack_bf16x2(acc[8*kt+4], acc[8*kt+5]);
                qf[kt][3] = pack_bf16x2(acc[8*kt+6], acc[8*kt+7]);
            }
        }

        // ================= scores: S[16x64] = q @ k^T (in registers) ==========
        float sacc[32];
#pragma unroll
        for (int i = 0; i < 32; i++) sacc[i] = 0.f;
#pragma unroll
        for (int kt = 0; kt < 4; kt++) {
#pragma unroll
            for (int nt2 = 0; nt2 < 4; nt2++) {
                uint32_t b[4];   // non-trans: B from sK[f_k][p]
                ldsm4(b, smb + OFF_K
                         + (bb * 64 + nt2 * 16 + (lane >> 4) * 8 + (lane & 7)) * 144
                         + (kt * 16 + ((lane >> 3) & 1) * 8) * 2);
                mma16816(&sacc[nt2 * 8],     qf[kt], b[0], b[1]);
                mma16816(&sacc[nt2 * 8 + 4], qf[kt], b[2], b[3]);
            }
        }
        // sacc[4j+b]   = S(row g,   col 8j+2q+b),  g = lane>>2, q = lane&3
        // sacc[4j+2+b] = S(row g+8, col 8j+2q+b)

        // ================= softmax over QUERY axis, register-resident ==========
        // Column = fixed (8j+2q+b); rows spread over lane>>2 within warp and
        // over the 4 warps of this batch. 3 shfl.xor rounds + SMEM exchange.
        float M[16];
#pragma unroll
        for (int j = 0; j < 8; j++) {
            M[2*j]   = fmaxf(sacc[4*j],   sacc[4*j+2]);
            M[2*j+1] = fmaxf(sacc[4*j+1], sacc[4*j+3]);
        }
#pragma unroll
        for (int o = 4; o <= 16; o <<= 1)
#pragma unroll
            for (int i = 0; i < 16; i++)
                M[i] = fmaxf(M[i], __shfl_xor_sync(0xffffffffu, M[i], o));
        if (lane < 4) {
            char* px = sm + OFF_XM + w4 * 576 + (bb * 72 + lane * 2) * 4;
#pragma unroll
            for (int j = 0; j < 8; j++)
                *(float2*)(px + j * 32) = make_float2(M[2*j], M[2*j+1]);
        }
        __syncthreads();
        {
            const char* px = sm + OFF_XM + (bb * 72 + (lane & 3) * 2) * 4;
#pragma unroll
            for (int j = 0; j < 8; j++) {
                float2 t0 = *(const float2*)(px +          j * 32);
                float2 t1 = *(const float2*)(px +  576  +  j * 32);
                float2 t2 = *(const float2*)(px + 1152  +  j * 32);
                float2 t3 = *(const float2*)(px + 1728  +  j * 32);
                M[2*j]   = fmaxf(fmaxf(t0.x, t1.x), fmaxf(t2.x, t3.x));
                M[2*j+1] = fmaxf(fmaxf(t0.y, t1.y), fmaxf(t2.y, t3.y));
            }
        }
        // exp in place
#pragma unroll
        for (int j = 0; j < 8; j++) {
            sacc[4*j]   = __expf(sacc[4*j]   - M[2*j]);
            sacc[4*j+1] = __expf(sacc[4*j+1] - M[2*j+1]);
            sacc[4*j+2] = __expf(sacc[4*j+2] - M[2*j]);
            sacc[4*j+3] = __expf(sacc[4*j+3] - M[2*j+1]);
        }
        // column sums (reuse M as sum regs)
#pragma unroll
        for (int j = 0; j < 8; j++) {
            M[2*j]   = sacc[4*j]   + sacc[4*j+2];
            M[2*j+1] = sacc[4*j+1] + sacc[4*j+3];
        }
#pragma unroll
        for (int o = 4; o <= 16; o <<= 1)
#pragma unroll
            for (int i = 0; i < 16; i++)
                M[i] += __shfl_xor_sync(0xffffffffu, M[i], o);
        if (lane < 4) {
            char* px = sm + OFF_XS + w4 * 576 + (bb * 72 + lane * 2) * 4;
#pragma unroll
            for (int j = 0; j < 8; j++)
                *(float2*)(px + j * 32) = make_float2(M[2*j], M[2*j+1]);
        }
        __syncthreads();
        uint32_t af[4][4];
        {
            const char* px = sm + OFF_XS + (bb * 72 + (lane & 3) * 2) * 4;
            float inv[16];
#pragma unroll
            for (int j = 0; j < 8; j++) {
                float2 t0 = *(const float2*)(px +         j * 32);
                float2 t1 = *(const float2*)(px +  576 +  j * 32);
                float2 t2 = *(const float2*)(px + 1152 +  j * 32);
                float2 t3 = *(const float2*)(px + 1728 +  j * 32);
                inv[2*j]   = 1.f / (t0.x + t1.x + t2.x + t3.x);
                inv[2*j+1] = 1.f / (t0.y + t1.y + t2.y + t3.y);
            }
            // att -> A-fragments directly (C layout == A layout)
#pragma unroll
            for (int kt = 0; kt < 4; kt++) {
                af[kt][0] = pack_bf16x2(sacc[8*kt]   * inv[4*kt],   sacc[8*kt+1] * inv[4*kt+1]);
                af[kt][1] = pack_bf16x2(sacc[8*kt+2] * inv[4*kt],   sacc[8*kt+3] * inv[4*kt+1]);
                af[kt][2] = pack_bf16x2(sacc[8*kt+4] * inv[4*kt+2], sacc[8*kt+5] * inv[4*kt+3]);
                af[kt][3] = pack_bf16x2(sacc[8*kt+6] * inv[4*kt+2], sacc[8*kt+7] * inv[4*kt+3]);
            }
        }

        // ================= stage Wr (sW free: all warps past q-proj) ==========
        stage_w(sm, Wr, h, tid);

        // ================= AV[16x64] = att @ v (A from af regs) ===============
        float avacc[32];
#pragma unroll
        for (int i = 0; i < 32; i++) avacc[i] = 0.f;
#pragma unroll
        for (int kt = 0; kt < 4; kt++) {
#pragma unroll
            for (int nt2 = 0; nt2 < 4; nt2++) {
                uint32_t b[4];   // trans: B from sV[f_k][p]
                ldsm4t(b, smb + OFF_V
                          + (bb * 64 + kt * 16 + (lane & 15)) * 144
                          + (nt2 * 16 + (lane >> 4) * 8) * 2);
                mma16816(&avacc[nt2 * 8],     af[kt], b[0], b[1]);
                mma16816(&avacc[nt2 * 8 + 4], af[kt], b[2], b[3]);
            }
        }
        __syncthreads();   // Wr staged

        // ================= r projection + fused epilogue =================
        {
            float acc[32];
            run_proj(acc, ea, smb + OFF_W, lane);

            int frow = (m0 & 63) + (lane >> 2);            // local feature row
            const float* ow = out_w + (size_t)h * Pn + (lane & 3) * 2;
#pragma unroll
            for (int j = 0; j < 8; j++) {
                float2 w0 = *(const float2*)(ow + (size_t)frow * (Hn * Pn) + j * 8);
                float2 w1 = *(const float2*)(ow + (size_t)(frow + 8) * (Hn * Pn) + j * 8);
                float v0 = avacc[4*j]   + acc[4*j];
                float v1 = avacc[4*j+1] + acc[4*j+1];
                float v2 = avacc[4*j+2] + acc[4*j+2];
                float v3 = avacc[4*j+3] + acc[4*j+3];
                if (v0 > 0.f) oacc += v0 * w0.x;
                if (v1 > 0.f) oacc += v1 * w0.y;
                if (v2 > 0.f) oacc += v2 * w1.x;
                if (v3 > 0.f) oacc += v3 * w1.y;
            }
        }
        __syncthreads();   // protect sW/sK/sV (+XM/XS) before next head
    }

    // ---- reduce: warps 0-3 -> batch0, 4-7 -> batch1
#pragma unroll
    for (int o = 16; o; o >>= 1) oacc += __shfl_xor_sync(0xffffffffu, oacc, o);
    if (lane == 0) sRed[wid] = oacc;
    __syncthreads();
    if (tid == 0) {
        float s = sRed[0] + sRed[1] + sRed[2] + sRed[3] + out_b[0];
        out[blockIdx.x * 2] = 1.f / (1.f + expf(-s));
    }
    if (tid == 1) {
        float s = sRed[4] + sRed[5] + sRed[6] + sRed[7] + out_b[0];
        out[blockIdx.x * 2 + 1] = 1.f / (1.f + expf(-s));
    }
}

extern "C" void kernel_launch(void* const* d_in, const int* in_sizes, int n_in,
                              void* d_out, int out_size)
{
    cudaFuncSetAttribute(autoint_mma, cudaFuncAttributeMaxDynamicSharedMemorySize, SMEM_BYTES);
    autoint_mma<<<Bn / 2, 256, SMEM_BYTES>>>(
        (const int*)d_in[0], (const float*)d_in[1],
        (const float*)d_in[2], (const float*)d_in[3],
        (const float*)d_in[4], (const float*)d_in[5],
        (const float*)d_in[6], (const float*)d_in[7], (float*)d_out);
}

// round 8
// speedup vs baseline: 9.8790x; 1.1459x over previous
#include <cuda_runtime.h>
#include <cuda_bf16.h>
#include <cstdint>
#include <math.h>

#define Bn 2048
#define Fn 64
#define Dn 128
#define Hn 8
#define Pn 64

namespace {
// SMEM byte offsets (16B-aligned rows; padded strides, no swizzle)
constexpr int OFF_IDX = 0;                    // 128 int
constexpr int OFF_RED = 512;                  // 8 float
constexpr int OFF_XS  = 576;                  // fp32 [4][144] sum-exchange
constexpr int OFF_E   = OFF_XS + 2304;        // bf16 [128][136] stride 272B
constexpr int OFF_W0  = OFF_E  + 128 * 272;   // bf16 [128][72]  stride 144B
constexpr int OFF_W1  = OFF_W0 + 128 * 144;   // bf16 [128][72]
constexpr int OFF_K   = OFF_W1 + 128 * 144;   // bf16 [128][72]
constexpr int OFF_V   = OFF_K  + 128 * 144;   // bf16 [128][72]
constexpr int SMEM_BYTES = OFF_V + 128 * 144; // 111424 B -> 2 CTAs/SM
}

__device__ __forceinline__ uint32_t smem_u32(const void* p) {
    uint32_t a;
    asm("{ .reg .u64 t; cvta.to.shared.u64 t, %1; cvt.u32.u64 %0, t; }" : "=r"(a) : "l"(p));
    return a;
}
__device__ __forceinline__ uint32_t pack_bf16x2(float lo, float hi) {
    uint32_t r;
    asm("cvt.rn.bf16x2.f32 %0, %1, %2;" : "=r"(r) : "f"(hi), "f"(lo));
    return r;
}
__device__ __forceinline__ void ldsm4(uint32_t* r, uint32_t addr) {
    asm volatile("ldmatrix.sync.aligned.m8n8.x4.shared.b16 {%0,%1,%2,%3}, [%4];"
                 : "=r"(r[0]), "=r"(r[1]), "=r"(r[2]), "=r"(r[3]) : "r"(addr));
}
__device__ __forceinline__ void ldsm4t(uint32_t* r, uint32_t addr) {
    asm volatile("ldmatrix.sync.aligned.m8n8.x4.trans.shared.b16 {%0,%1,%2,%3}, [%4];"
                 : "=r"(r[0]), "=r"(r[1]), "=r"(r[2]), "=r"(r[3]) : "r"(addr));
}
__device__ __forceinline__ void mma16816(float* c, const uint32_t* a, uint32_t b0, uint32_t b1) {
    asm volatile(
        "mma.sync.aligned.m16n8k16.row.col.f32.bf16.bf16.f32 "
        "{%0,%1,%2,%3}, {%4,%5,%6,%7}, {%8,%9}, {%0,%1,%2,%3};"
        : "+f"(c[0]), "+f"(c[1]), "+f"(c[2]), "+f"(c[3])
        : "r"(a[0]), "r"(a[1]), "r"(a[2]), "r"(a[3]), "r"(b0), "r"(b1));
}

// C[16x64] = E[16x128] @ W[128x64]; A from hoisted E frags, B via ldmatrix.trans
__device__ __forceinline__ void run_proj(float acc[32], const uint32_t ea[8][4],
                                         uint32_t wbase, int lane) {
#pragma unroll
    for (int i = 0; i < 32; i++) acc[i] = 0.f;
#pragma unroll
    for (int kt = 0; kt < 8; kt++) {
#pragma unroll
        for (int nt2 = 0; nt2 < 4; nt2++) {
            uint32_t b[4];
            ldsm4t(b, wbase + (kt * 16 + (lane & 15)) * 144
                          + (nt2 * 16 + (lane >> 4) * 8) * 2);
            mma16816(&acc[nt2 * 8],     ea[kt], b[0], b[1]);
            mma16816(&acc[nt2 * 8 + 4], ea[kt], b[2], b[3]);
        }
    }
}

// stage two W head-slices at once: threads 0-127 -> (Wa, W0), 128-255 -> (Wb, W1)
__device__ __forceinline__ void stage_w2(char* sm, const float* Wa, const float* Wb,
                                         int h, int tid) {
    const float* W = (tid < 128) ? Wa : Wb;
    char* base = sm + ((tid < 128) ? OFF_W0 : OFF_W1);
    int t = tid & 127;
#pragma unroll
    for (int it = 0; it < 32; it++) {
        int i = t + it * 128;               // 128*32 bf16x2
        int row = i >> 5, c2 = i & 31;
        float2 v = *(const float2*)(W + row * (Hn * Pn) + h * Pn + 2 * c2);
        *(uint32_t*)(base + row * 144 + c2 * 4) = pack_bf16x2(v.x, v.y);
    }
}

__global__ __launch_bounds__(256, 2)
void autoint_mma(const int*   __restrict__ feat_index,
                 const float* __restrict__ emb,
                 const float* __restrict__ Wq, const float* __restrict__ Wk,
                 const float* __restrict__ Wv, const float* __restrict__ Wr,
                 const float* __restrict__ out_w, const float* __restrict__ out_b,
                 float* __restrict__ out)
{
    extern __shared__ char sm[];
    const uint32_t smb = smem_u32(sm);
    const int tid  = threadIdx.x;
    const int wid  = tid >> 5;
    const int lane = tid & 31;
    const int m0   = wid * 16;        // warp's M-row base for attention (0..112)
    const int bb   = wid >> 2;        // batch slot (0/1)
    const int w4   = wid & 3;         // warp index within batch

    int*   sIdx = (int*)(sm + OFF_IDX);
    float* sRed = (float*)(sm + OFF_RED);

    if (tid < 128) sIdx[tid] = feat_index[(size_t)blockIdx.x * 128 + tid];
    __syncthreads();

    // ---- gather E -> bf16 [128][136]
#pragma unroll
    for (int it = 0; it < 32; it++) {
        int i = tid + it * 256;
        int row = i >> 6, c2 = i & 63;
        float2 v = *(const float2*)(emb + (size_t)sIdx[row] * Dn + 2 * c2);
        *(uint32_t*)(sm + OFF_E + row * 272 + c2 * 4) = pack_bf16x2(v.x, v.y);
    }
    __syncthreads();

    // ---- hoist E A-fragments for this warp's 16 attention rows
    uint32_t ea[8][4];
#pragma unroll
    for (int kt = 0; kt < 8; kt++)
        ldsm4(ea[kt], smb + OFF_E + (m0 + (lane & 15)) * 272
                          + (kt * 16 + (lane >> 4) * 8) * 2);

    float oacc = 0.f;

    for (int h = 0; h < Hn; h++) {
        // ================= stage Wk->W0, Wv->W1 =================
        stage_w2(sm, Wk, Wv, h, tid);
        __syncthreads();                                   // sync A

        // ================= paired k|v projections, 32 rows/warp =================
        // warps 0-3: k from W0 -> sK ; warps 4-7: v from W1 -> sV
        {
            const int mrow = w4 * 32;
            const uint32_t wb = smb + ((wid < 4) ? OFF_W0 : OFF_W1);
            char* po = sm + ((wid < 4) ? OFF_K : OFF_V);
            float acc0[32], acc1[32];
#pragma unroll
            for (int i = 0; i < 32; i++) { acc0[i] = 0.f; acc1[i] = 0.f; }
#pragma unroll
            for (int kt = 0; kt < 8; kt++) {
                uint32_t a0[4], a1[4];
                uint32_t ab = smb + OFF_E + (mrow + (lane & 15)) * 272
                                  + (kt * 16 + (lane >> 4) * 8) * 2;
                ldsm4(a0, ab);
                ldsm4(a1, ab + 16 * 272);
#pragma unroll
                for (int nt2 = 0; nt2 < 4; nt2++) {
                    uint32_t b[4];
                    ldsm4t(b, wb + (kt * 16 + (lane & 15)) * 144
                                  + (nt2 * 16 + (lane >> 4) * 8) * 2);
                    mma16816(&acc0[nt2 * 8],     a0, b[0], b[1]);
                    mma16816(&acc0[nt2 * 8 + 4], a0, b[2], b[3]);
                    mma16816(&acc1[nt2 * 8],     a1, b[0], b[1]);
                    mma16816(&acc1[nt2 * 8 + 4], a1, b[2], b[3]);
                }
            }
#pragma unroll
            for (int mt = 0; mt < 2; mt++) {
                const float* acc = mt ? acc1 : acc0;
                char* p0 = po + (mrow + mt * 16 + (lane >> 2)) * 144 + (lane & 3) * 4;
#pragma unroll
                for (int j = 0; j < 8; j++) {
                    *(uint32_t*)(p0 + j * 16)           = pack_bf16x2(acc[4*j],   acc[4*j+1]);
                    *(uint32_t*)(p0 + 8 * 144 + j * 16) = pack_bf16x2(acc[4*j+2], acc[4*j+3]);
                }
            }
        }
        __syncthreads();                                   // sync B (sK/sV ready, W free)

        // ================= stage Wq->W0, Wr->W1 =================
        stage_w2(sm, Wq, Wr, h, tid);
        __syncthreads();                                   // sync C

        // ================= q projection -> A-fragments =================
        uint32_t qf[4][4];
        {
            float acc[32];
            run_proj(acc, ea, smb + OFF_W0, lane);
#pragma unroll
            for (int kt = 0; kt < 4; kt++) {
                qf[kt][0] = pack_bf16x2(acc[8*kt],   acc[8*kt+1]);
                qf[kt][1] = pack_bf16x2(acc[8*kt+2], acc[8*kt+3]);
                qf[kt][2] = pack_bf16x2(acc[8*kt+4], acc[8*kt+5]);
                qf[kt][3] = pack_bf16x2(acc[8*kt+6], acc[8*kt+7]);
            }
        }

        // ================= scores: S[16x64] = q @ k^T (in registers) ==========
        float sacc[32];
#pragma unroll
        for (int i = 0; i < 32; i++) sacc[i] = 0.f;
#pragma unroll
        for (int kt = 0; kt < 4; kt++) {
#pragma unroll
            for (int nt2 = 0; nt2 < 4; nt2++) {
                uint32_t b[4];   // non-trans: B from sK[f_k][p]
                ldsm4(b, smb + OFF_K
                         + (bb * 64 + nt2 * 16 + (lane >> 4) * 8 + (lane & 7)) * 144
                         + (kt * 16 + ((lane >> 3) & 1) * 8) * 2);
                mma16816(&sacc[nt2 * 8],     qf[kt], b[0], b[1]);
                mma16816(&sacc[nt2 * 8 + 4], qf[kt], b[2], b[3]);
            }
        }

        // ================= softmax over QUERY axis (no max-shift: scores O(0.3))
#pragma unroll
        for (int i = 0; i < 32; i++) sacc[i] = __expf(sacc[i]);
        float M[16];
#pragma unroll
        for (int j = 0; j < 8; j++) {
            M[2*j]   = sacc[4*j]   + sacc[4*j+2];
            M[2*j+1] = sacc[4*j+1] + sacc[4*j+3];
        }
#pragma unroll
        for (int o = 4; o <= 16; o <<= 1)
#pragma unroll
            for (int i = 0; i < 16; i++)
                M[i] += __shfl_xor_sync(0xffffffffu, M[i], o);
        if (lane < 4) {
            char* px = sm + OFF_XS + w4 * 576 + (bb * 72 + lane * 2) * 4;
#pragma unroll
            for (int j = 0; j < 8; j++)
                *(float2*)(px + j * 32) = make_float2(M[2*j], M[2*j+1]);
        }
        __syncthreads();                                   // sync D
        uint32_t af[4][4];
        {
            const char* px = sm + OFF_XS + (bb * 72 + (lane & 3) * 2) * 4;
            float inv[16];
#pragma unroll
            for (int j = 0; j < 8; j++) {
                float2 t0 = *(const float2*)(px +         j * 32);
                float2 t1 = *(const float2*)(px +  576 +  j * 32);
                float2 t2 = *(const float2*)(px + 1152 +  j * 32);
                float2 t3 = *(const float2*)(px + 1728 +  j * 32);
                inv[2*j]   = 1.f / (t0.x + t1.x + t2.x + t3.x);
                inv[2*j+1] = 1.f / (t0.y + t1.y + t2.y + t3.y);
            }
            // att -> A-fragments directly (C layout == A layout)
#pragma unroll
            for (int kt = 0; kt < 4; kt++) {
                af[kt][0] = pack_bf16x2(sacc[8*kt]   * inv[4*kt],   sacc[8*kt+1] * inv[4*kt+1]);
                af[kt][1] = pack_bf16x2(sacc[8*kt+2] * inv[4*kt],   sacc[8*kt+3] * inv[4*kt+1]);
                af[kt][2] = pack_bf16x2(sacc[8*kt+4] * inv[4*kt+2], sacc[8*kt+5] * inv[4*kt+3]);
                af[kt][3] = pack_bf16x2(sacc[8*kt+6] * inv[4*kt+2], sacc[8*kt+7] * inv[4*kt+3]);
            }
        }

        // ================= AV[16x64] = att @ v =================
        float avacc[32];
#pragma unroll
        for (int i = 0; i < 32; i++) avacc[i] = 0.f;
#pragma unroll
        for (int kt = 0; kt < 4; kt++) {
#pragma unroll
            for (int nt2 = 0; nt2 < 4; nt2++) {
                uint32_t b[4];   // trans: B from sV[f_k][p]
                ldsm4t(b, smb + OFF_V
                          + (bb * 64 + kt * 16 + (lane & 15)) * 144
                          + (nt2 * 16 + (lane >> 4) * 8) * 2);
                mma16816(&avacc[nt2 * 8],     af[kt], b[0], b[1]);
                mma16816(&avacc[nt2 * 8 + 4], af[kt], b[2], b[3]);
            }
        }

        // ================= r projection (W1, staged at sync C) + epilogue ======
        {
            float acc[32];
            run_proj(acc, ea, smb + OFF_W1, lane);

            int frow = (m0 & 63) + (lane >> 2);            // local feature row
            const float* ow = out_w + (size_t)h * Pn + (lane & 3) * 2;
#pragma unroll
            for (int j = 0; j < 8; j++) {
                float2 w0 = *(const float2*)(ow + (size_t)frow * (Hn * Pn) + j * 8);
                float2 w1 = *(const float2*)(ow + (size_t)(frow + 8) * (Hn * Pn) + j * 8);
                float v0 = avacc[4*j]   + acc[4*j];
                float v1 = avacc[4*j+1] + acc[4*j+1];
                float v2 = avacc[4*j+2] + acc[4*j+2];
                float v3 = avacc[4*j+3] + acc[4*j+3];
                if (v0 > 0.f) oacc += v0 * w0.x;
                if (v1 > 0.f) oacc += v1 * w0.y;
                if (v2 > 0.f) oacc += v2 * w1.x;
                if (v3 > 0.f) oacc += v3 * w1.y;
            }
        }
        __syncthreads();                                   // sync E (protect all tiles)
    }

    // ---- reduce: warps 0-3 -> batch0, 4-7 -> batch1
#pragma unroll
    for (int o = 16; o; o >>= 1) oacc += __shfl_xor_sync(0xffffffffu, oacc, o);
    if (lane == 0) sRed[wid] = oacc;
    __syncthreads();
    if (tid == 0) {
        float s = sRed[0] + sRed[1] + sRed[2] + sRed[3] + out_b[0];
        out[blockIdx.x * 2] = 1.f / (1.f + expf(-s));
    }
    if (tid == 1) {
        float s = sRed[4] + sRed[5] + sRed[6] + sRed[7] + out_b[0];
        out[blockIdx.x * 2 + 1] = 1.f / (1.f + expf(-s));
    }
}

extern "C" void kernel_launch(void* const* d_in, const int* in_sizes, int n_in,
                              void* d_out, int out_size)
{
    cudaFuncSetAttribute(autoint_mma, cudaFuncAttributeMaxDynamicSharedMemorySize, SMEM_BYTES);
    autoint_mma<<<Bn / 2, 256, SMEM_BYTES>>>(
        (const int*)d_in[0], (const float*)d_in[1],
        (const float*)d_in[2], (const float*)d_in[3],
        (const float*)d_in[4], (const float*)d_in[5],
        (const float*)d_in[6], (const float*)d_in[7], (float*)d_out);
}